// round 10
// baseline (speedup 1.0000x reference)
#include <cuda_runtime.h>
#include <math.h>

// Problem constants (fixed by the dataset)
#define NNODES   50000
#define FEAT     144        // C_RAD * SH_DIM
#define CRAD     16
#define SHD      9
#define NRBF     128
#define CUTOFF   5.0f
#define TBL      8192       // radial-table resolution
#define SLOTS    64         // edge-id bucket slots per node (overflow -> fallback)
#define OVF_CAP  8192

// node_kernel tiling
#define NTILE    64         // nodes per block
#define VSTRIDE  148        // smem feature-row stride (floats; 16B-aligned rows, conflict-free)
#define NWARP    12         // warps per block; each owns 12 j's

// ---------------- device scratch (no allocs allowed) ----------------
__device__ float g_table[(TBL + 1) * CRAD];     // rad(d) lookup (+ sentinel row)
__device__ float g_deg[(size_t)NNODES * FEAT];  // aggregated, PRE-SCALED by 1/sqrt(deg_avg)
__device__ int   g_cnt[NNODES];                 // per-dst (near-)edge count
__device__ int   g_eid[(size_t)NNODES * SLOTS]; // bucketed edge ids
__device__ int   g_ovf[OVF_CAP];                // overflow edge ids
__device__ int   g_ovfcnt;
__device__ int   g_skipfar;                     // 1 if biases are all zero -> far edges contribute 0

#define INV_SQRT_DEG   0.25335570773f   // 1/sqrt(15.57930850982666)
#define INV_SQRT_NODES 0.23549661171f   // 1/sqrt(18.03065905448718)

__device__ __forceinline__ float silu_f(float x) {
    return x / (1.0f + expf(-x));
}

// f32x2 packed-FMA helpers (sm_103a)
__device__ __forceinline__ unsigned long long pk2(float lo, float hi) {
    unsigned long long r;
    asm("mov.b64 %0, {%1, %2};" : "=l"(r) : "f"(lo), "f"(hi));
    return r;
}
__device__ __forceinline__ void fma2(unsigned long long& d,
                                     unsigned long long a, unsigned long long b) {
    asm("fma.rn.f32x2 %0, %1, %2, %0;" : "+l"(d) : "l"(a), "l"(b));
}
__device__ __forceinline__ void unpk2(unsigned long long v, float& lo, float& hi) {
    asm("mov.b64 {%0, %1}, %2;" : "=f"(lo), "=f"(hi) : "l"(v));
}

// per-edge geometry: rad[16] (table interp) + sh[9]
__device__ __forceinline__ void edge_geom(float vx, float vy, float vz,
                                          float* rad, float* sh) {
    const float len = sqrtf(vx * vx + vy * vy + vz * vz);
    const float inv = 1.0f / fmaxf(len, 1e-12f);
    const float x = vx * inv, y = vy * inv, z = vz * inv;

    const float s3 = 1.7320508075688772f;
    const float s5 = 2.23606797749979f;
    const float s15 = 3.872983346207417f;
    sh[0] = 1.0f;
    sh[1] = s3 * x; sh[2] = s3 * y; sh[3] = s3 * z;
    sh[4] = s15 * x * z;
    sh[5] = s15 * x * y;
    sh[6] = s5 * (y * y - 0.5f * (x * x + z * z));
    sh[7] = s15 * y * z;
    sh[8] = 0.5f * s15 * (z * z - x * x);

    float u = len * ((float)TBL / CUTOFF);
    u = fminf(u, (float)TBL);
    int i0 = min((int)u, TBL - 1);
    float f = u - (float)i0;
    const float4* t0 = reinterpret_cast<const float4*>(g_table + (size_t)i0 * CRAD);
    const float4* t1 = reinterpret_cast<const float4*>(g_table + (size_t)(i0 + 1) * CRAD);
    #pragma unroll
    for (int q = 0; q < 4; q++) {
        float4 a = t0[q], b = t1[q];
        rad[4 * q + 0] = fmaf(f, b.x - a.x, a.x);
        rad[4 * q + 1] = fmaf(f, b.y - a.y, a.y);
        rad[4 * q + 2] = fmaf(f, b.z - a.z, a.z);
        rad[4 * q + 3] = fmaf(f, b.w - a.w, a.w);
    }
}

// ---------------- kernel A: zero counters + output + bias check ----------------
__global__ void zero_kernel(float* __restrict__ out, int G,
                            const float* __restrict__ b1, const float* __restrict__ b2) {
    __shared__ int s_nz;
    const int i = blockIdx.x * blockDim.x + threadIdx.x;
    if (i < NNODES) g_cnt[i] = 0;
    if (i < G) out[i] = 0.0f;
    if (i == 0) g_ovfcnt = 0;
    if (blockIdx.x == 0) {
        if (threadIdx.x == 0) s_nz = 0;
        __syncthreads();
        if (threadIdx.x < 64 && (b1[threadIdx.x] != 0.0f || b2[threadIdx.x] != 0.0f))
            atomicAdd(&s_nz, 1);
        __syncthreads();
        if (threadIdx.x == 0) g_skipfar = (s_nz == 0) ? 1 : 0;
    }
}

// ---------------- kernel B (fat): radial table + filtered edge bucketing ----------------
__global__ void __launch_bounds__(256) fat_kernel(const float* __restrict__ W1, const float* __restrict__ b1,
                                                  const float* __restrict__ W2, const float* __restrict__ b2,
                                                  const float* __restrict__ W3,
                                                  const int* __restrict__ esrc,
                                                  const int* __restrict__ edst,
                                                  const float* __restrict__ pos, int E) {
    if (blockIdx.x < TBL + 1) {
        __shared__ float s_rbf[NRBF];
        __shared__ float s_h1[64];
        __shared__ float s_h2[64];

        const int i = blockIdx.x;
        const int t = threadIdx.x;
        const float d = (float)i * (CUTOFF / (float)TBL);

        const double startd = 0.006737946999085467;          // exp(-5)
        const double width  = (2.0 / 128.0) * (1.0 - startd);
        const float  BETA   = (float)(1.0 / (width * width));

        if (t < NRBF) {
            const float mean = (float)(startd + (1.0 - startd) * ((double)t / 127.0));
            float cut = 0.0f;
            if (d < CUTOFF)
                cut = 0.5f * (cosf(d * (float)(3.14159265358979323846 / 5.0)) + 1.0f);
            const float ex = expf(-d);
            const float dd = ex - mean;
            s_rbf[t] = cut * expf(-BETA * dd * dd);
        }
        __syncthreads();

        if (t < 64) {
            float a = b1[t];
            #pragma unroll 8
            for (int k = 0; k < NRBF; k++) a = fmaf(s_rbf[k], W1[k * 64 + t], a);
            s_h1[t] = silu_f(a);
        }
        __syncthreads();
        if (t < 64) {
            float a = b2[t];
            #pragma unroll 8
            for (int k = 0; k < 64; k++) a = fmaf(s_h1[k], W2[k * 64 + t], a);
            s_h2[t] = silu_f(a);
        }
        __syncthreads();
        if (t < CRAD) {
            float a = 0.0f;
            #pragma unroll 8
            for (int k = 0; k < 64; k++) a = fmaf(s_h2[k], W3[k * CRAD + t], a);
            g_table[i * CRAD + t] = a;
        }
    } else {
        const int e = (blockIdx.x - (TBL + 1)) * 256 + threadIdx.x;
        if (e < E) {
            const int d = edst[e];
            bool keep = true;
            if (g_skipfar) {
                const int s = esrc[e];
                const float vx = pos[3 * (size_t)s + 0] - pos[3 * (size_t)d + 0];
                const float vy = pos[3 * (size_t)s + 1] - pos[3 * (size_t)d + 1];
                const float vz = pos[3 * (size_t)s + 2] - pos[3 * (size_t)d + 2];
                keep = (vx * vx + vy * vy + vz * vz) < (CUTOFF * CUTOFF);
            }
            if (keep) {
                const int pos_i = atomicAdd(&g_cnt[d], 1);
                if (pos_i < SLOTS) {
                    g_eid[(size_t)d * SLOTS + pos_i] = e;
                } else {
                    const int oi = atomicAdd(&g_ovfcnt, 1);
                    if (oi < OVF_CAP) g_ovf[oi] = e;
                }
            }
        }
    }
}

// ---------------- kernel C: warp-per-node gather ----------------
__global__ void __launch_bounds__(256) gather_kernel(const float* __restrict__ pos,
                                                     const int* __restrict__ esrc,
                                                     int N) {
    __shared__ float sE[8][32][29];   // [warp][edge][rad16|sh9|pad]

    const int w = threadIdx.x >> 5;           // warp in block
    const int lane = threadIdx.x & 31;
    const int n = blockIdx.x * 8 + w;         // node
    if (n >= N) return;

    const int deg = g_cnt[n];
    const int nslot = min(deg, SLOTS);

    const float pdx = pos[3 * (size_t)n + 0];
    const float pdy = pos[3 * (size_t)n + 1];
    const float pdz = pos[3 * (size_t)n + 2];

    const int c = lane >> 1;
    const int h = lane & 1;
    const int k0 = h ? 5 : 0;
    const int nk = h ? 4 : 5;

    float acc[5] = {0.f, 0.f, 0.f, 0.f, 0.f};

    for (int base = 0; base < nslot; base += 32) {
        const int cnt = min(nslot - base, 32);
        float rad[CRAD], sh[SHD];
        if (lane < cnt) {
            const int e = g_eid[(size_t)n * SLOTS + base + lane];
            const int s = esrc[e];
            const float vx = pos[3 * (size_t)s + 0] - pdx;
            const float vy = pos[3 * (size_t)s + 1] - pdy;
            const float vz = pos[3 * (size_t)s + 2] - pdz;
            edge_geom(vx, vy, vz, rad, sh);
            #pragma unroll
            for (int q = 0; q < CRAD; q++) sE[w][lane][q] = rad[q];
            #pragma unroll
            for (int q = 0; q < SHD; q++) sE[w][lane][CRAD + q] = sh[q];
        }
        __syncwarp();
        for (int e2 = 0; e2 < cnt; e2++) {
            const float r = sE[w][e2][c];
            #pragma unroll
            for (int m = 0; m < 5; m++) {
                if (m < nk) acc[m] = fmaf(r, sE[w][e2][CRAD + k0 + m], acc[m]);
            }
        }
        __syncwarp();
    }

    float* dst = g_deg + (size_t)n * FEAT + 9 * c + k0;
    #pragma unroll
    for (int m = 0; m < 5; m++) {
        if (m < nk) dst[m] = acc[m] * INV_SQRT_DEG;
    }
}

// ---------------- kernel D: node head GEMM ----------------
// 384 threads = 12 warps, 2 blocks/SM. Warp w owns j in [12w, 12w+12).
// Lane ln owns nodes ln and ln+32 of the 64-node tile.
// W: warp-uniform __ldg float4 (1 wavefront, L1-resident: only 38KB smem carveout).
// V: smem, LDS.128 per 4 k's, stride 148 (phase-conflict-free).
__global__ void __launch_bounds__(NWARP * 32, 2) node_kernel(const float* __restrict__ atab,
                                                             const int* __restrict__ natom,
                                                             const float* __restrict__ Wh1,
                                                             const float* __restrict__ bh1,
                                                             const float* __restrict__ Wh2,
                                                             const float* __restrict__ bh2,
                                                             const int* __restrict__ batch,
                                                             const float* __restrict__ pos,
                                                             const int* __restrict__ esrc,
                                                             const int* __restrict__ edst,
                                                             float* __restrict__ out,
                                                             int N) {
    extern __shared__ float sV[];          // [NTILE][VSTRIDE] = 37,888 B
    __shared__ int s_batch[NTILE];

    const int t = threadIdx.x;
    const int w = t >> 5;                  // warp id: j0 = 12*w
    const int ln = t & 31;
    const int nb = blockIdx.x * NTILE;

    // stage node features: atab[natom] + g_deg (pre-scaled)
    for (int idx = t; idx < NTILE * (FEAT / 2); idx += NWARP * 32) {
        const int n = idx / (FEAT / 2);
        const int kk = idx - n * (FEAT / 2);
        const int k = 2 * kk;
        const int gn = nb + n;
        float v0 = 0.0f, v1 = 0.0f;
        if (gn < N) {
            const float2 a = *reinterpret_cast<const float2*>(atab + (size_t)natom[gn] * FEAT + k);
            const float2 g = *reinterpret_cast<const float2*>(g_deg + (size_t)gn * FEAT + k);
            v0 = a.x + g.x;
            v1 = a.y + g.y;
        }
        sV[n * VSTRIDE + k]     = v0;
        sV[n * VSTRIDE + k + 1] = v1;
    }
    if (t < NTILE) {
        const int gn = nb + t;
        s_batch[t] = (gn < N) ? batch[gn] : 0;
    }
    __syncthreads();

    // overflow fixup (practically never taken for this graph)
    const int novf = g_ovfcnt;
    if (novf > 0) {
        for (int i = t; i < min(novf, OVF_CAP); i += NWARP * 32) {
            const int e = g_ovf[i];
            const int d = edst[e];
            if (d >= nb && d < nb + NTILE && d < N) {
                const int s = esrc[e];
                const float vx = pos[3 * (size_t)s + 0] - pos[3 * (size_t)d + 0];
                const float vy = pos[3 * (size_t)s + 1] - pos[3 * (size_t)d + 1];
                const float vz = pos[3 * (size_t)s + 2] - pos[3 * (size_t)d + 2];
                float rad[CRAD], sh[SHD];
                edge_geom(vx, vy, vz, rad, sh);
                for (int j = 0; j < FEAT; j++) {
                    atomicAdd(&sV[(d - nb) * VSTRIDE + j],
                              rad[j / SHD] * sh[j % SHD] * INV_SQRT_DEG);
                }
            }
        }
        __syncthreads();
    }

    const int j0 = 12 * w;
    const float* Wj = Wh1 + j0;

    unsigned long long acc[2][6];          // [node q][j-pair]
    #pragma unroll
    for (int q = 0; q < 2; q++)
        #pragma unroll
        for (int p = 0; p < 6; p++) acc[q][p] = 0ULL;

    #pragma unroll 2
    for (int k4 = 0; k4 < FEAT / 4; k4++) {
        float va[4], vb[4];
        *reinterpret_cast<float4*>(va) = *reinterpret_cast<const float4*>(&sV[ln * VSTRIDE + 4 * k4]);
        *reinterpret_cast<float4*>(vb) = *reinterpret_cast<const float4*>(&sV[(ln + 32) * VSTRIDE + 4 * k4]);
        #pragma unroll
        for (int kk = 0; kk < 4; kk++) {
            const int k = 4 * k4 + kk;
            const float4 w0 = __ldg(reinterpret_cast<const float4*>(Wj + (size_t)k * FEAT));
            const float4 w1 = __ldg(reinterpret_cast<const float4*>(Wj + (size_t)k * FEAT + 4));
            const float4 w2 = __ldg(reinterpret_cast<const float4*>(Wj + (size_t)k * FEAT + 8));
            const unsigned long long p0 = pk2(w0.x, w0.y);
            const unsigned long long p1 = pk2(w0.z, w0.w);
            const unsigned long long p2 = pk2(w1.x, w1.y);
            const unsigned long long p3 = pk2(w1.z, w1.w);
            const unsigned long long p4 = pk2(w2.x, w2.y);
            const unsigned long long p5 = pk2(w2.z, w2.w);
            const unsigned long long vva = pk2(va[kk], va[kk]);
            const unsigned long long vvb = pk2(vb[kk], vb[kk]);
            fma2(acc[0][0], vva, p0);
            fma2(acc[0][1], vva, p1);
            fma2(acc[0][2], vva, p2);
            fma2(acc[0][3], vva, p3);
            fma2(acc[0][4], vva, p4);
            fma2(acc[0][5], vva, p5);
            fma2(acc[1][0], vvb, p0);
            fma2(acc[1][1], vvb, p1);
            fma2(acc[1][2], vvb, p2);
            fma2(acc[1][3], vvb, p3);
            fma2(acc[1][4], vvb, p4);
            fma2(acc[1][5], vvb, p5);
        }
    }

    // epilogue: silu + dot with Wh2 slice, partial-energy atomics
    float bj[12], w2v[12];
    #pragma unroll
    for (int p = 0; p < 12; p++) {
        bj[p] = bh1[j0 + p];
        w2v[p] = Wh2[j0 + p];
    }
    const float bias2 = bh2[0];

    #pragma unroll
    for (int q = 0; q < 2; q++) {
        const int n = ln + 32 * q;
        const int gn = nb + n;
        if (gn >= N) continue;
        float p = 0.0f;
        #pragma unroll
        for (int pp = 0; pp < 6; pp++) {
            float a0, a1;
            unpk2(acc[q][pp], a0, a1);
            p += silu_f(a0 + bj[2 * pp])     * w2v[2 * pp];
            p += silu_f(a1 + bj[2 * pp + 1]) * w2v[2 * pp + 1];
        }
        if (w == 0) p += bias2;
        atomicAdd(out + s_batch[n], p * INV_SQRT_NODES);
    }
}

#define NODE_SMEM (NTILE * VSTRIDE * 4)

// ---------------- launcher ----------------
extern "C" void kernel_launch(void* const* d_in, const int* in_sizes, int n_in,
                              void* d_out, int out_size) {
    const float* pos  = (const float*)d_in[0];
    const float* atab = (const float*)d_in[1];
    const float* W1   = (const float*)d_in[2];
    const float* b1   = (const float*)d_in[3];
    const float* W2   = (const float*)d_in[4];
    const float* b2   = (const float*)d_in[5];
    const float* W3   = (const float*)d_in[6];
    const float* Wh1  = (const float*)d_in[7];
    const float* bh1  = (const float*)d_in[8];
    const float* Wh2  = (const float*)d_in[9];
    const float* bh2  = (const float*)d_in[10];
    const int* natom  = (const int*)d_in[11];
    const int* esrc   = (const int*)d_in[12];
    const int* edst   = (const int*)d_in[13];
    const int* batch  = (const int*)d_in[14];
    float* out = (float*)d_out;

    const int N = in_sizes[11];
    const int E = in_sizes[12];
    const int G = out_size;

    static bool attr_done = false;
    if (!attr_done) {
        cudaFuncSetAttribute(node_kernel,
                             cudaFuncAttributeMaxDynamicSharedMemorySize, NODE_SMEM);
        attr_done = true;
    }

    // 1: zero counters + output, bias all-zero check
    zero_kernel<<<(NNODES + 255) / 256, 256>>>(out, G, b1, b2);

    // 2: radial table + cutoff-filtered edge bucketing
    const int scatter_blocks = (E + 255) / 256;
    fat_kernel<<<(TBL + 1) + scatter_blocks, 256>>>(W1, b1, W2, b2, W3, esrc, edst, pos, E);

    // 3: warp-per-node gather
    gather_kernel<<<(N + 7) / 8, 256>>>(pos, esrc, N);

    // 4: node GEMM + head + graph reduction — profiled launch
    node_kernel<<<(N + NTILE - 1) / NTILE, NWARP * 32, NODE_SMEM>>>(
        atab, natom, Wh1, bh1, Wh2, bh2, batch, pos, esrc, edst, out, N);
}